// round 7
// baseline (speedup 1.0000x reference)
#include <cuda_runtime.h>
#include <cuda_bf16.h>

#define OUT_F 4096
#define IN_F  2048
#define KDIM  4096   // 2*IN_F logical K
#define BATCH 4096

// Dense decompressed weight scratch (64 MB) — __device__ global, no allocation.
__device__ float g_Wd[(size_t)OUT_F * KDIM];

// ---------------------------------------------------------------------------
// Kernel 1: decompress (weight, metadata) -> dense logical-K weight g_Wd.
// One thread per group of 4 logical columns (2 compressed elements).
// ---------------------------------------------------------------------------
__global__ void decompress_kernel(const float* __restrict__ w,
                                  const int* __restrict__ meta) {
    int idx = blockIdx.x * blockDim.x + threadIdx.x;   // r * 1024 + g
    int r = idx >> 10;
    int g = idx & 1023;
    const float2 wv = *reinterpret_cast<const float2*>(w    + (size_t)r * IN_F + 2 * g);
    const int2   mv = *reinterpret_cast<const int2*>  (meta + (size_t)r * IN_F + 2 * g);
    // mv.x, mv.y in 0..3, distinct (sorted pair from LUT)
    float4 v;
    v.x = (mv.x == 0) ? wv.x : ((mv.y == 0) ? wv.y : 0.f);
    v.y = (mv.x == 1) ? wv.x : ((mv.y == 1) ? wv.y : 0.f);
    v.z = (mv.x == 2) ? wv.x : ((mv.y == 2) ? wv.y : 0.f);
    v.w = (mv.x == 3) ? wv.x : ((mv.y == 3) ? wv.y : 0.f);
    *reinterpret_cast<float4*>(g_Wd + (size_t)r * KDIM + 4 * g) = v;
}

// ---------------------------------------------------------------------------
// Kernel 2: SGEMM D = Wd @ input^T over compressed rows, scatter epilogue.
// Block tile 128x128, K-tile 8, 256 threads, 8x8 micro-tile per thread.
// Smem rows padded to 132 floats: conflict-free transposed STS, aligned LDS.128.
// ---------------------------------------------------------------------------
#define BM 128
#define BN 128
#define BK 8
#define LDA 132   // padded row length (floats); 132*4 = 528 B (16B-aligned)

__global__ __launch_bounds__(256, 2) void sgemm_scatter_kernel(
    const float* __restrict__ Bmat,     // input [BATCH][KDIM], K-contiguous
    const int*   __restrict__ indices,  // [OUT_F] logical row ids
    float*       __restrict__ out)      // [2*OUT_F][BATCH]
{
    __shared__ float As[BK][LDA];
    __shared__ float Bs[BK][LDA];

    const int tid = threadIdx.x;
    const int tx  = tid & 15;   // 16 cols of threads -> N
    const int ty  = tid >> 4;   // 16 rows of threads -> M

    const float* Aptr = g_Wd + (size_t)blockIdx.y * BM * KDIM;
    const float* Bptr = Bmat + (size_t)blockIdx.x * BN * KDIM;

    const int ld_row = tid >> 1;          // 0..127
    const int ld_col = (tid & 1) * 4;     // 0 or 4

    float acc[8][8] = {};

    // prefetch first K-tile into registers
    float4 a = *reinterpret_cast<const float4*>(Aptr + (size_t)ld_row * KDIM + ld_col);
    float4 b = *reinterpret_cast<const float4*>(Bptr + (size_t)ld_row * KDIM + ld_col);

    for (int k0 = 0; k0 < KDIM; k0 += BK) {
        As[ld_col + 0][ld_row] = a.x; As[ld_col + 1][ld_row] = a.y;
        As[ld_col + 2][ld_row] = a.z; As[ld_col + 3][ld_row] = a.w;
        Bs[ld_col + 0][ld_row] = b.x; Bs[ld_col + 1][ld_row] = b.y;
        Bs[ld_col + 2][ld_row] = b.z; Bs[ld_col + 3][ld_row] = b.w;
        __syncthreads();

        if (k0 + BK < KDIM) {   // prefetch next K-tile (hides GMEM latency)
            a = *reinterpret_cast<const float4*>(Aptr + (size_t)ld_row * KDIM + (k0 + BK) + ld_col);
            b = *reinterpret_cast<const float4*>(Bptr + (size_t)ld_row * KDIM + (k0 + BK) + ld_col);
        }

        #pragma unroll
        for (int kk = 0; kk < BK; kk++) {
            float4 a0 = *reinterpret_cast<const float4*>(&As[kk][ty * 8]);
            float4 a1 = *reinterpret_cast<const float4*>(&As[kk][ty * 8 + 4]);
            float4 b0 = *reinterpret_cast<const float4*>(&Bs[kk][tx * 8]);
            float4 b1 = *reinterpret_cast<const float4*>(&Bs[kk][tx * 8 + 4]);
            float ar[8] = {a0.x, a0.y, a0.z, a0.w, a1.x, a1.y, a1.z, a1.w};
            float br[8] = {b0.x, b0.y, b0.z, b0.w, b1.x, b1.y, b1.z, b1.w};
            #pragma unroll
            for (int i = 0; i < 8; i++)
                #pragma unroll
                for (int j = 0; j < 8; j++)
                    acc[i][j] += ar[i] * br[j];
        }
        __syncthreads();
    }

    // Epilogue: scatter computed rows; zero sibling rows (covers full output).
    const int n0 = blockIdx.x * BN + tx * 8;
    const float4 z4 = make_float4(0.f, 0.f, 0.f, 0.f);
    #pragma unroll
    for (int i = 0; i < 8; i++) {
        int r   = blockIdx.y * BM + ty * 8 + i;
        int idx = indices[r];
        float* orow = out + (size_t)idx * BATCH + n0;
        float* zrow = out + (size_t)(idx ^ 1) * BATCH + n0;
        *reinterpret_cast<float4*>(orow)     = make_float4(acc[i][0], acc[i][1], acc[i][2], acc[i][3]);
        *reinterpret_cast<float4*>(orow + 4) = make_float4(acc[i][4], acc[i][5], acc[i][6], acc[i][7]);
        *reinterpret_cast<float4*>(zrow)     = z4;
        *reinterpret_cast<float4*>(zrow + 4) = z4;
    }
}

// ---------------------------------------------------------------------------
extern "C" void kernel_launch(void* const* d_in, const int* in_sizes, int n_in,
                              void* d_out, int out_size) {
    const float* weight   = (const float*)d_in[0];
    const int*   indices  = (const int*)  d_in[1];
    const int*   metadata = (const int*)  d_in[2];
    const float* input    = (const float*)d_in[3];
    float*       out      = (float*)d_out;

    // 1 thread per 4 logical cols: OUT_F * IN_F/2 threads
    decompress_kernel<<<(OUT_F * (IN_F / 2)) / 256, 256>>>(weight, metadata);

    dim3 grid(BATCH / BN, OUT_F / BM);
    sgemm_scatter_kernel<<<grid, 256>>>(input, indices, out);
}

// round 12
// speedup vs baseline: 2.3155x; 2.3155x over previous
#include <cuda_runtime.h>
#include <cuda_bf16.h>

#define OUT_F 4096
#define IN_F  2048
#define KDIM  4096
#define BATCH 4096

#define BM 128
#define BN 256
#define BKE 32                    // K elems per chunk (2 x k16 mma steps)
#define NCHUNK (KDIM / BKE)       // 128

// ---- bf16 hi/lo scratch (128 MB total) ----
__device__ __nv_bfloat16 g_Ahi[(size_t)OUT_F * KDIM];
__device__ __nv_bfloat16 g_Alo[(size_t)OUT_F * KDIM];
__device__ __nv_bfloat16 g_Bhi[(size_t)BATCH * KDIM];
__device__ __nv_bfloat16 g_Blo[(size_t)BATCH * KDIM];

// ---------------------------------------------------------------------------
// helpers (all arch-portable PTX: sm_80-class, safe under compute_103)
// ---------------------------------------------------------------------------
__device__ __forceinline__ unsigned smem_u32(const void* p) {
    unsigned a;
    asm("{ .reg .u64 t; cvta.to.shared.u64 t, %1; cvt.u32.u64 %0, t; }" : "=r"(a) : "l"(p));
    return a;
}
__device__ __forceinline__ void cp16(unsigned dst, const void* src) {
    asm volatile("cp.async.cg.shared.global [%0], [%1], 16;" :: "r"(dst), "l"(src));
}
#define CP_COMMIT() asm volatile("cp.async.commit_group;" ::: "memory")

__device__ __forceinline__ void ldsm4(unsigned* r, unsigned addr) {
    asm volatile("ldmatrix.sync.aligned.m8n8.x4.shared.b16 {%0,%1,%2,%3}, [%4];"
                 : "=r"(r[0]), "=r"(r[1]), "=r"(r[2]), "=r"(r[3]) : "r"(addr));
}
__device__ __forceinline__ void mma16816(float* d, const unsigned* a, const unsigned* b) {
    asm volatile("mma.sync.aligned.m16n8k16.row.col.f32.bf16.bf16.f32 "
                 "{%0,%1,%2,%3}, {%4,%5,%6,%7}, {%8,%9}, {%0,%1,%2,%3};"
                 : "+f"(d[0]), "+f"(d[1]), "+f"(d[2]), "+f"(d[3])
                 : "r"(a[0]), "r"(a[1]), "r"(a[2]), "r"(a[3]), "r"(b[0]), "r"(b[1]));
}

// ---------------------------------------------------------------------------
// Convert kernels: fp32 -> bf16 hi + bf16 lo (with sparse decompression for W)
// ---------------------------------------------------------------------------
__global__ void convert_w(const float* __restrict__ w, const int* __restrict__ meta) {
    int idx = blockIdx.x * 256 + threadIdx.x;   // r*1024 + g
    int r = idx >> 10, g = idx & 1023;
    const float2 wv = *reinterpret_cast<const float2*>(w    + (size_t)r * IN_F + 2 * g);
    const int2   mv = *reinterpret_cast<const int2*>  (meta + (size_t)r * IN_F + 2 * g);
    float v0 = (mv.x == 0) ? wv.x : ((mv.y == 0) ? wv.y : 0.f);
    float v1 = (mv.x == 1) ? wv.x : ((mv.y == 1) ? wv.y : 0.f);
    float v2 = (mv.x == 2) ? wv.x : ((mv.y == 2) ? wv.y : 0.f);
    float v3 = (mv.x == 3) ? wv.x : ((mv.y == 3) ? wv.y : 0.f);
    __nv_bfloat16 h0 = __float2bfloat16(v0), h1 = __float2bfloat16(v1);
    __nv_bfloat16 h2 = __float2bfloat16(v2), h3 = __float2bfloat16(v3);
    __nv_bfloat16 l0 = __float2bfloat16(v0 - __bfloat162float(h0));
    __nv_bfloat16 l1 = __float2bfloat16(v1 - __bfloat162float(h1));
    __nv_bfloat16 l2 = __float2bfloat16(v2 - __bfloat162float(h2));
    __nv_bfloat16 l3 = __float2bfloat16(v3 - __bfloat162float(h3));
    uint2 ph, pl;
    ph.x = (unsigned)__bfloat16_as_ushort(h0) | ((unsigned)__bfloat16_as_ushort(h1) << 16);
    ph.y = (unsigned)__bfloat16_as_ushort(h2) | ((unsigned)__bfloat16_as_ushort(h3) << 16);
    pl.x = (unsigned)__bfloat16_as_ushort(l0) | ((unsigned)__bfloat16_as_ushort(l1) << 16);
    pl.y = (unsigned)__bfloat16_as_ushort(l2) | ((unsigned)__bfloat16_as_ushort(l3) << 16);
    *reinterpret_cast<uint2*>(g_Ahi + (size_t)r * KDIM + 4 * g) = ph;
    *reinterpret_cast<uint2*>(g_Alo + (size_t)r * KDIM + 4 * g) = pl;
}

__global__ void convert_in(const float* __restrict__ in) {
    int idx = blockIdx.x * 256 + threadIdx.x;   // row*1024 + g
    int r = idx >> 10, g = idx & 1023;
    const float4 v = *reinterpret_cast<const float4*>(in + (size_t)r * KDIM + 4 * g);
    __nv_bfloat16 h0 = __float2bfloat16(v.x), h1 = __float2bfloat16(v.y);
    __nv_bfloat16 h2 = __float2bfloat16(v.z), h3 = __float2bfloat16(v.w);
    __nv_bfloat16 l0 = __float2bfloat16(v.x - __bfloat162float(h0));
    __nv_bfloat16 l1 = __float2bfloat16(v.y - __bfloat162float(h1));
    __nv_bfloat16 l2 = __float2bfloat16(v.z - __bfloat162float(h2));
    __nv_bfloat16 l3 = __float2bfloat16(v.w - __bfloat162float(h3));
    uint2 ph, pl;
    ph.x = (unsigned)__bfloat16_as_ushort(h0) | ((unsigned)__bfloat16_as_ushort(h1) << 16);
    ph.y = (unsigned)__bfloat16_as_ushort(h2) | ((unsigned)__bfloat16_as_ushort(h3) << 16);
    pl.x = (unsigned)__bfloat16_as_ushort(l0) | ((unsigned)__bfloat16_as_ushort(l1) << 16);
    pl.y = (unsigned)__bfloat16_as_ushort(l2) | ((unsigned)__bfloat16_as_ushort(l3) << 16);
    *reinterpret_cast<uint2*>(g_Bhi + (size_t)r * KDIM + 4 * g) = ph;
    *reinterpret_cast<uint2*>(g_Blo + (size_t)r * KDIM + 4 * g) = pl;
}

// ---------------------------------------------------------------------------
// mma.sync GEMM: CTA 128x256, 8 warps (2M x 4N), warp tile 64x64.
// K-chunk 32 bf16 (64B/row), smem rows padded to 80B (conflict-free, 16B-aligned).
// ---------------------------------------------------------------------------
#define ROWB 80
#define OFF_AHI 0
#define OFF_ALO (BM * ROWB)                    // 10240
#define OFF_BHI (2 * BM * ROWB)                // 20480
#define OFF_BLO (2 * BM * ROWB + BN * ROWB)    // 40960
#define STAGE_BYTES (2 * (BM + BN) * ROWB)     // 61440
#define NSTAGE 3
#define SMEM_DYN (NSTAGE * STAGE_BYTES)        // 184320

__device__ __forceinline__ void load_chunk(unsigned stage, int m0, int n0, int k0, int tid) {
    #pragma unroll
    for (int j = 0; j < 2; j++) {              // A hi: 128 rows x 4 chunks
        int id = tid + (j << 8);
        int r = id >> 2, c = id & 3;
        cp16(stage + OFF_AHI + r * ROWB + c * 16,
             g_Ahi + ((size_t)(m0 + r) << 12) + k0 + (c << 3));
    }
    #pragma unroll
    for (int j = 0; j < 2; j++) {              // A lo
        int id = tid + (j << 8);
        int r = id >> 2, c = id & 3;
        cp16(stage + OFF_ALO + r * ROWB + c * 16,
             g_Alo + ((size_t)(m0 + r) << 12) + k0 + (c << 3));
    }
    #pragma unroll
    for (int j = 0; j < 4; j++) {              // B hi: 256 rows x 4 chunks
        int id = tid + (j << 8);
        int r = id >> 2, c = id & 3;
        cp16(stage + OFF_BHI + r * ROWB + c * 16,
             g_Bhi + ((size_t)(n0 + r) << 12) + k0 + (c << 3));
    }
    #pragma unroll
    for (int j = 0; j < 4; j++) {              // B lo
        int id = tid + (j << 8);
        int r = id >> 2, c = id & 3;
        cp16(stage + OFF_BLO + r * ROWB + c * 16,
             g_Blo + ((size_t)(n0 + r) << 12) + k0 + (c << 3));
    }
    CP_COMMIT();
}

__global__ __launch_bounds__(256, 1) void gemm_kernel(const int* __restrict__ indices,
                                                      float* __restrict__ out) {
    extern __shared__ char smem[];
    const unsigned sb = smem_u32(smem);
    const int tid = threadIdx.x, wid = tid >> 5, lane = tid & 31;
    const int wm = wid & 1, wn = wid >> 1;     // 2(M) x 4(N) warps
    const int sub = lane >> 3, lrow = lane & 7;

    const int tn = blockIdx.x & 15, tm = blockIdx.x >> 4;
    const int m0 = tm * BM, n0 = tn * BN;

    // per-thread ldmatrix base offsets (within a stage)
    // A frag (m16k16): sub0:(row,klo) sub1:(row+8,klo) sub2:(row,khi) sub3:(row+8,khi)
    const unsigned aoff = (unsigned)((wm * 64 + lrow + (sub & 1) * 8) * ROWB + (sub >> 1) * 16);
    // B frag pair (two n8k16): sub0:(row,klo) sub1:(row,khi) sub2:(row+8,klo) sub3:(row+8,khi)
    const unsigned boff = (unsigned)((wn * 64 + lrow + (sub >> 1) * 8) * ROWB + (sub & 1) * 16);

    float d[4][8][4];
    #pragma unroll
    for (int a = 0; a < 4; a++)
        #pragma unroll
        for (int b = 0; b < 8; b++)
            #pragma unroll
            for (int c = 0; c < 4; c++) d[a][b][c] = 0.f;

    load_chunk(sb,                   m0, n0, 0,       tid);
    load_chunk(sb + STAGE_BYTES,     m0, n0, BKE,     tid);

    int stage_idx = 0;
    for (int i = 0; i < NCHUNK; i++) {
        asm volatile("cp.async.wait_group 1;" ::: "memory");
        __syncthreads();
        const unsigned stg = sb + stage_idx * STAGE_BYTES;

        #pragma unroll
        for (int ks = 0; ks < 2; ks++) {
            unsigned ah[4][4], al[4][4], bh[4][4], bl[4][4];
            #pragma unroll
            for (int mt = 0; mt < 4; mt++) {
                ldsm4(ah[mt], stg + OFF_AHI + aoff + mt * (16 * ROWB) + ks * 32);
                ldsm4(al[mt], stg + OFF_ALO + aoff + mt * (16 * ROWB) + ks * 32);
            }
            #pragma unroll
            for (int p = 0; p < 4; p++) {
                ldsm4(bh[p], stg + OFF_BHI + boff + p * (16 * ROWB) + ks * 32);
                ldsm4(bl[p], stg + OFF_BLO + boff + p * (16 * ROWB) + ks * 32);
            }
            #pragma unroll
            for (int mt = 0; mt < 4; mt++)
                #pragma unroll
                for (int p = 0; p < 4; p++) {
                    mma16816(d[mt][2 * p],     ah[mt], &bh[p][0]);
                    mma16816(d[mt][2 * p + 1], ah[mt], &bh[p][2]);
                    mma16816(d[mt][2 * p],     ah[mt], &bl[p][0]);
                    mma16816(d[mt][2 * p + 1], ah[mt], &bl[p][2]);
                    mma16816(d[mt][2 * p],     al[mt], &bh[p][0]);
                    mma16816(d[mt][2 * p + 1], al[mt], &bh[p][2]);
                }
        }
        __syncthreads();
        if (i + 2 < NCHUNK)
            load_chunk(sb + ((stage_idx + 2) % NSTAGE) * STAGE_BYTES, m0, n0, (i + 2) * BKE, tid);
        else
            CP_COMMIT();
        stage_idx = (stage_idx + 1) % NSTAGE;
    }

    // Epilogue: scatter rows by indices, zero sibling rows.
    const int ncol = n0 + wn * 64 + 2 * (lane & 3);
    #pragma unroll
    for (int mt = 0; mt < 4; mt++) {
        #pragma unroll
        for (int h = 0; h < 2; h++) {
            const int r = m0 + wm * 64 + mt * 16 + h * 8 + (lane >> 2);
            const int idx = indices[r];
            float* orow = out + (size_t)idx * BATCH + ncol;
            float* zrow = out + (size_t)(idx ^ 1) * BATCH + ncol;
            #pragma unroll
            for (int j = 0; j < 8; j++) {
                float2 v = make_float2(d[mt][j][2 * h], d[mt][j][2 * h + 1]);
                *reinterpret_cast<float2*>(orow + 8 * j) = v;
                *reinterpret_cast<float2*>(zrow + 8 * j) = make_float2(0.f, 0.f);
            }
        }
    }
}

// ---------------------------------------------------------------------------
extern "C" void kernel_launch(void* const* d_in, const int* in_sizes, int n_in,
                              void* d_out, int out_size) {
    const float* weight   = (const float*)d_in[0];
    const int*   indices  = (const int*)  d_in[1];
    const int*   metadata = (const int*)  d_in[2];
    const float* input    = (const float*)d_in[3];
    float*       out      = (float*)d_out;

    cudaFuncSetAttribute(gemm_kernel, cudaFuncAttributeMaxDynamicSharedMemorySize, SMEM_DYN);

    convert_w<<<(OUT_F * (IN_F / 2)) / 256, 256>>>(weight, metadata);
    convert_in<<<(BATCH * (KDIM / 4)) / 256, 256>>>(input);
    gemm_kernel<<<(OUT_F / BM) * (BATCH / BN), 256, SMEM_DYN>>>(indices, out);
}

// round 13
// speedup vs baseline: 2.3156x; 1.0000x over previous
#include <cuda_runtime.h>
#include <cuda_bf16.h>

#define OUT_F 4096
#define IN_F  2048
#define KDIM  4096
#define BATCH 4096

#define BM 128
#define BN 256
#define BKE 32                    // K elems per chunk (2 x k16 mma steps)
#define NCHUNK (KDIM / BKE)       // 128

// ---- bf16 hi/lo scratch (128 MB total) ----
__device__ __nv_bfloat16 g_Ahi[(size_t)OUT_F * KDIM];
__device__ __nv_bfloat16 g_Alo[(size_t)OUT_F * KDIM];
__device__ __nv_bfloat16 g_Bhi[(size_t)BATCH * KDIM];
__device__ __nv_bfloat16 g_Blo[(size_t)BATCH * KDIM];

// ---------------------------------------------------------------------------
// helpers (all arch-portable PTX: sm_80-class, safe under compute_103)
// ---------------------------------------------------------------------------
__device__ __forceinline__ unsigned smem_u32(const void* p) {
    unsigned a;
    asm("{ .reg .u64 t; cvta.to.shared.u64 t, %1; cvt.u32.u64 %0, t; }" : "=r"(a) : "l"(p));
    return a;
}
__device__ __forceinline__ void cp16(unsigned dst, const void* src) {
    asm volatile("cp.async.cg.shared.global [%0], [%1], 16;" :: "r"(dst), "l"(src));
}
#define CP_COMMIT() asm volatile("cp.async.commit_group;" ::: "memory")

__device__ __forceinline__ void ldsm4(unsigned* r, unsigned addr) {
    asm volatile("ldmatrix.sync.aligned.m8n8.x4.shared.b16 {%0,%1,%2,%3}, [%4];"
                 : "=r"(r[0]), "=r"(r[1]), "=r"(r[2]), "=r"(r[3]) : "r"(addr));
}
__device__ __forceinline__ void mma16816(float* d, const unsigned* a, const unsigned* b) {
    asm volatile("mma.sync.aligned.m16n8k16.row.col.f32.bf16.bf16.f32 "
                 "{%0,%1,%2,%3}, {%4,%5,%6,%7}, {%8,%9}, {%0,%1,%2,%3};"
                 : "+f"(d[0]), "+f"(d[1]), "+f"(d[2]), "+f"(d[3])
                 : "r"(a[0]), "r"(a[1]), "r"(a[2]), "r"(a[3]), "r"(b[0]), "r"(b[1]));
}

// ---------------------------------------------------------------------------
// Convert kernels: fp32 -> bf16 hi + bf16 lo (with sparse decompression for W)
// ---------------------------------------------------------------------------
__global__ void convert_w(const float* __restrict__ w, const int* __restrict__ meta) {
    int idx = blockIdx.x * 256 + threadIdx.x;   // r*1024 + g
    int r = idx >> 10, g = idx & 1023;
    const float2 wv = *reinterpret_cast<const float2*>(w    + (size_t)r * IN_F + 2 * g);
    const int2   mv = *reinterpret_cast<const int2*>  (meta + (size_t)r * IN_F + 2 * g);
    float v0 = (mv.x == 0) ? wv.x : ((mv.y == 0) ? wv.y : 0.f);
    float v1 = (mv.x == 1) ? wv.x : ((mv.y == 1) ? wv.y : 0.f);
    float v2 = (mv.x == 2) ? wv.x : ((mv.y == 2) ? wv.y : 0.f);
    float v3 = (mv.x == 3) ? wv.x : ((mv.y == 3) ? wv.y : 0.f);
    __nv_bfloat16 h0 = __float2bfloat16(v0), h1 = __float2bfloat16(v1);
    __nv_bfloat16 h2 = __float2bfloat16(v2), h3 = __float2bfloat16(v3);
    __nv_bfloat16 l0 = __float2bfloat16(v0 - __bfloat162float(h0));
    __nv_bfloat16 l1 = __float2bfloat16(v1 - __bfloat162float(h1));
    __nv_bfloat16 l2 = __float2bfloat16(v2 - __bfloat162float(h2));
    __nv_bfloat16 l3 = __float2bfloat16(v3 - __bfloat162float(h3));
    uint2 ph, pl;
    ph.x = (unsigned)__bfloat16_as_ushort(h0) | ((unsigned)__bfloat16_as_ushort(h1) << 16);
    ph.y = (unsigned)__bfloat16_as_ushort(h2) | ((unsigned)__bfloat16_as_ushort(h3) << 16);
    pl.x = (unsigned)__bfloat16_as_ushort(l0) | ((unsigned)__bfloat16_as_ushort(l1) << 16);
    pl.y = (unsigned)__bfloat16_as_ushort(l2) | ((unsigned)__bfloat16_as_ushort(l3) << 16);
    *reinterpret_cast<uint2*>(g_Ahi + (size_t)r * KDIM + 4 * g) = ph;
    *reinterpret_cast<uint2*>(g_Alo + (size_t)r * KDIM + 4 * g) = pl;
}

__global__ void convert_in(const float* __restrict__ in) {
    int idx = blockIdx.x * 256 + threadIdx.x;   // row*1024 + g
    int r = idx >> 10, g = idx & 1023;
    const float4 v = *reinterpret_cast<const float4*>(in + (size_t)r * KDIM + 4 * g);
    __nv_bfloat16 h0 = __float2bfloat16(v.x), h1 = __float2bfloat16(v.y);
    __nv_bfloat16 h2 = __float2bfloat16(v.z), h3 = __float2bfloat16(v.w);
    __nv_bfloat16 l0 = __float2bfloat16(v.x - __bfloat162float(h0));
    __nv_bfloat16 l1 = __float2bfloat16(v.y - __bfloat162float(h1));
    __nv_bfloat16 l2 = __float2bfloat16(v.z - __bfloat162float(h2));
    __nv_bfloat16 l3 = __float2bfloat16(v.w - __bfloat162float(h3));
    uint2 ph, pl;
    ph.x = (unsigned)__bfloat16_as_ushort(h0) | ((unsigned)__bfloat16_as_ushort(h1) << 16);
    ph.y = (unsigned)__bfloat16_as_ushort(h2) | ((unsigned)__bfloat16_as_ushort(h3) << 16);
    pl.x = (unsigned)__bfloat16_as_ushort(l0) | ((unsigned)__bfloat16_as_ushort(l1) << 16);
    pl.y = (unsigned)__bfloat16_as_ushort(l2) | ((unsigned)__bfloat16_as_ushort(l3) << 16);
    *reinterpret_cast<uint2*>(g_Bhi + (size_t)r * KDIM + 4 * g) = ph;
    *reinterpret_cast<uint2*>(g_Blo + (size_t)r * KDIM + 4 * g) = pl;
}

// ---------------------------------------------------------------------------
// mma.sync GEMM: CTA 128x256, 8 warps (2M x 4N), warp tile 64x64.
// K-chunk 32 bf16 (64B/row), smem rows padded to 80B (conflict-free, 16B-aligned).
// ---------------------------------------------------------------------------
#define ROWB 80
#define OFF_AHI 0
#define OFF_ALO (BM * ROWB)                    // 10240
#define OFF_BHI (2 * BM * ROWB)                // 20480
#define OFF_BLO (2 * BM * ROWB + BN * ROWB)    // 40960
#define STAGE_BYTES (2 * (BM + BN) * ROWB)     // 61440
#define NSTAGE 3
#define SMEM_DYN (NSTAGE * STAGE_BYTES)        // 184320

__device__ __forceinline__ void load_chunk(unsigned stage, int m0, int n0, int k0, int tid) {
    #pragma unroll
    for (int j = 0; j < 2; j++) {              // A hi: 128 rows x 4 chunks
        int id = tid + (j << 8);
        int r = id >> 2, c = id & 3;
        cp16(stage + OFF_AHI + r * ROWB + c * 16,
             g_Ahi + ((size_t)(m0 + r) << 12) + k0 + (c << 3));
    }
    #pragma unroll
    for (int j = 0; j < 2; j++) {              // A lo
        int id = tid + (j << 8);
        int r = id >> 2, c = id & 3;
        cp16(stage + OFF_ALO + r * ROWB + c * 16,
             g_Alo + ((size_t)(m0 + r) << 12) + k0 + (c << 3));
    }
    #pragma unroll
    for (int j = 0; j < 4; j++) {              // B hi: 256 rows x 4 chunks
        int id = tid + (j << 8);
        int r = id >> 2, c = id & 3;
        cp16(stage + OFF_BHI + r * ROWB + c * 16,
             g_Bhi + ((size_t)(n0 + r) << 12) + k0 + (c << 3));
    }
    #pragma unroll
    for (int j = 0; j < 4; j++) {              // B lo
        int id = tid + (j << 8);
        int r = id >> 2, c = id & 3;
        cp16(stage + OFF_BLO + r * ROWB + c * 16,
             g_Blo + ((size_t)(n0 + r) << 12) + k0 + (c << 3));
    }
    CP_COMMIT();
}

__global__ __launch_bounds__(256, 1) void gemm_kernel(const int* __restrict__ indices,
                                                      float* __restrict__ out) {
    extern __shared__ char smem[];
    const unsigned sb = smem_u32(smem);
    const int tid = threadIdx.x, wid = tid >> 5, lane = tid & 31;
    const int wm = wid & 1, wn = wid >> 1;     // 2(M) x 4(N) warps
    const int sub = lane >> 3, lrow = lane & 7;

    const int tn = blockIdx.x & 15, tm = blockIdx.x >> 4;
    const int m0 = tm * BM, n0 = tn * BN;

    // per-thread ldmatrix base offsets (within a stage)
    // A frag (m16k16): sub0:(row,klo) sub1:(row+8,klo) sub2:(row,khi) sub3:(row+8,khi)
    const unsigned aoff = (unsigned)((wm * 64 + lrow + (sub & 1) * 8) * ROWB + (sub >> 1) * 16);
    // B frag pair (two n8k16): sub0:(row,klo) sub1:(row,khi) sub2:(row+8,klo) sub3:(row+8,khi)
    const unsigned boff = (unsigned)((wn * 64 + lrow + (sub >> 1) * 8) * ROWB + (sub & 1) * 16);

    float d[4][8][4];
    #pragma unroll
    for (int a = 0; a < 4; a++)
        #pragma unroll
        for (int b = 0; b < 8; b++)
            #pragma unroll
            for (int c = 0; c < 4; c++) d[a][b][c] = 0.f;

    load_chunk(sb,                   m0, n0, 0,       tid);
    load_chunk(sb + STAGE_BYTES,     m0, n0, BKE,     tid);

    int stage_idx = 0;
    for (int i = 0; i < NCHUNK; i++) {
        asm volatile("cp.async.wait_group 1;" ::: "memory");
        __syncthreads();
        const unsigned stg = sb + stage_idx * STAGE_BYTES;

        #pragma unroll
        for (int ks = 0; ks < 2; ks++) {
            unsigned ah[4][4], al[4][4], bh[4][4], bl[4][4];
            #pragma unroll
            for (int mt = 0; mt < 4; mt++) {
                ldsm4(ah[mt], stg + OFF_AHI + aoff + mt * (16 * ROWB) + ks * 32);
                ldsm4(al[mt], stg + OFF_ALO + aoff + mt * (16 * ROWB) + ks * 32);
            }
            #pragma unroll
            for (int p = 0; p < 4; p++) {
                ldsm4(bh[p], stg + OFF_BHI + boff + p * (16 * ROWB) + ks * 32);
                ldsm4(bl[p], stg + OFF_BLO + boff + p * (16 * ROWB) + ks * 32);
            }
            #pragma unroll
            for (int mt = 0; mt < 4; mt++)
                #pragma unroll
                for (int p = 0; p < 4; p++) {
                    mma16816(d[mt][2 * p],     ah[mt], &bh[p][0]);
                    mma16816(d[mt][2 * p + 1], ah[mt], &bh[p][2]);
                    mma16816(d[mt][2 * p],     ah[mt], &bl[p][0]);
                    mma16816(d[mt][2 * p + 1], ah[mt], &bl[p][2]);
                    mma16816(d[mt][2 * p],     al[mt], &bh[p][0]);
                    mma16816(d[mt][2 * p + 1], al[mt], &bh[p][2]);
                }
        }
        __syncthreads();
        if (i + 2 < NCHUNK)
            load_chunk(sb + ((stage_idx + 2) % NSTAGE) * STAGE_BYTES, m0, n0, (i + 2) * BKE, tid);
        else
            CP_COMMIT();
        stage_idx = (stage_idx + 1) % NSTAGE;
    }

    // Epilogue: scatter rows by indices, zero sibling rows.
    const int ncol = n0 + wn * 64 + 2 * (lane & 3);
    #pragma unroll
    for (int mt = 0; mt < 4; mt++) {
        #pragma unroll
        for (int h = 0; h < 2; h++) {
            const int r = m0 + wm * 64 + mt * 16 + h * 8 + (lane >> 2);
            const int idx = indices[r];
            float* orow = out + (size_t)idx * BATCH + ncol;
            float* zrow = out + (size_t)(idx ^ 1) * BATCH + ncol;
            #pragma unroll
            for (int j = 0; j < 8; j++) {
                float2 v = make_float2(d[mt][j][2 * h], d[mt][j][2 * h + 1]);
                *reinterpret_cast<float2*>(orow + 8 * j) = v;
                *reinterpret_cast<float2*>(zrow + 8 * j) = make_float2(0.f, 0.f);
            }
        }
    }
}

// ---------------------------------------------------------------------------
extern "C" void kernel_launch(void* const* d_in, const int* in_sizes, int n_in,
                              void* d_out, int out_size) {
    const float* weight   = (const float*)d_in[0];
    const int*   indices  = (const int*)  d_in[1];
    const int*   metadata = (const int*)  d_in[2];
    const float* input    = (const float*)d_in[3];
    float*       out      = (float*)d_out;

    cudaFuncSetAttribute(gemm_kernel, cudaFuncAttributeMaxDynamicSharedMemorySize, SMEM_DYN);

    convert_w<<<(OUT_F * (IN_F / 2)) / 256, 256>>>(weight, metadata);
    convert_in<<<(BATCH * (KDIM / 4)) / 256, 256>>>(input);
    gemm_kernel<<<(OUT_F / BM) * (BATCH / BN), 256, SMEM_DYN>>>(indices, out);
}

// round 14
// speedup vs baseline: 2.3165x; 1.0004x over previous
#include <cuda_runtime.h>
#include <cuda_bf16.h>

#define OUT_F 4096
#define IN_F  2048
#define KDIM  4096
#define BATCH 4096

#define BM 128
#define BN 256
#define BKE 32                    // K elems per chunk (2 x k16 mma steps)
#define NCHUNK (KDIM / BKE)       // 128

// ---- bf16 hi/lo scratch (128 MB total) ----
__device__ __nv_bfloat16 g_Ahi[(size_t)OUT_F * KDIM];
__device__ __nv_bfloat16 g_Alo[(size_t)OUT_F * KDIM];
__device__ __nv_bfloat16 g_Bhi[(size_t)BATCH * KDIM];
__device__ __nv_bfloat16 g_Blo[(size_t)BATCH * KDIM];

// ---------------------------------------------------------------------------
// helpers (all arch-portable PTX: sm_80-class, safe under compute_103)
// ---------------------------------------------------------------------------
__device__ __forceinline__ unsigned smem_u32(const void* p) {
    unsigned a;
    asm("{ .reg .u64 t; cvta.to.shared.u64 t, %1; cvt.u32.u64 %0, t; }" : "=r"(a) : "l"(p));
    return a;
}
__device__ __forceinline__ void cp16(unsigned dst, const void* src) {
    asm volatile("cp.async.cg.shared.global [%0], [%1], 16;" :: "r"(dst), "l"(src));
}
#define CP_COMMIT() asm volatile("cp.async.commit_group;" ::: "memory")

__device__ __forceinline__ void ldsm4(unsigned* r, unsigned addr) {
    asm volatile("ldmatrix.sync.aligned.m8n8.x4.shared.b16 {%0,%1,%2,%3}, [%4];"
                 : "=r"(r[0]), "=r"(r[1]), "=r"(r[2]), "=r"(r[3]) : "r"(addr));
}
__device__ __forceinline__ void mma16816(float* d, const unsigned* a, const unsigned* b) {
    asm volatile("mma.sync.aligned.m16n8k16.row.col.f32.bf16.bf16.f32 "
                 "{%0,%1,%2,%3}, {%4,%5,%6,%7}, {%8,%9}, {%0,%1,%2,%3};"
                 : "+f"(d[0]), "+f"(d[1]), "+f"(d[2]), "+f"(d[3])
                 : "r"(a[0]), "r"(a[1]), "r"(a[2]), "r"(a[3]), "r"(b[0]), "r"(b[1]));
}

// ---------------------------------------------------------------------------
// Convert kernels: fp32 -> bf16 hi + bf16 lo (with sparse decompression for W)
// ---------------------------------------------------------------------------
__global__ void convert_w(const float* __restrict__ w, const int* __restrict__ meta) {
    int idx = blockIdx.x * 256 + threadIdx.x;   // r*1024 + g
    int r = idx >> 10, g = idx & 1023;
    const float2 wv = *reinterpret_cast<const float2*>(w    + (size_t)r * IN_F + 2 * g);
    const int2   mv = *reinterpret_cast<const int2*>  (meta + (size_t)r * IN_F + 2 * g);
    float v0 = (mv.x == 0) ? wv.x : ((mv.y == 0) ? wv.y : 0.f);
    float v1 = (mv.x == 1) ? wv.x : ((mv.y == 1) ? wv.y : 0.f);
    float v2 = (mv.x == 2) ? wv.x : ((mv.y == 2) ? wv.y : 0.f);
    float v3 = (mv.x == 3) ? wv.x : ((mv.y == 3) ? wv.y : 0.f);
    __nv_bfloat16 h0 = __float2bfloat16(v0), h1 = __float2bfloat16(v1);
    __nv_bfloat16 h2 = __float2bfloat16(v2), h3 = __float2bfloat16(v3);
    __nv_bfloat16 l0 = __float2bfloat16(v0 - __bfloat162float(h0));
    __nv_bfloat16 l1 = __float2bfloat16(v1 - __bfloat162float(h1));
    __nv_bfloat16 l2 = __float2bfloat16(v2 - __bfloat162float(h2));
    __nv_bfloat16 l3 = __float2bfloat16(v3 - __bfloat162float(h3));
    uint2 ph, pl;
    ph.x = (unsigned)__bfloat16_as_ushort(h0) | ((unsigned)__bfloat16_as_ushort(h1) << 16);
    ph.y = (unsigned)__bfloat16_as_ushort(h2) | ((unsigned)__bfloat16_as_ushort(h3) << 16);
    pl.x = (unsigned)__bfloat16_as_ushort(l0) | ((unsigned)__bfloat16_as_ushort(l1) << 16);
    pl.y = (unsigned)__bfloat16_as_ushort(l2) | ((unsigned)__bfloat16_as_ushort(l3) << 16);
    *reinterpret_cast<uint2*>(g_Ahi + (size_t)r * KDIM + 4 * g) = ph;
    *reinterpret_cast<uint2*>(g_Alo + (size_t)r * KDIM + 4 * g) = pl;
}

__global__ void convert_in(const float* __restrict__ in) {
    int idx = blockIdx.x * 256 + threadIdx.x;   // row*1024 + g
    int r = idx >> 10, g = idx & 1023;
    const float4 v = *reinterpret_cast<const float4*>(in + (size_t)r * KDIM + 4 * g);
    __nv_bfloat16 h0 = __float2bfloat16(v.x), h1 = __float2bfloat16(v.y);
    __nv_bfloat16 h2 = __float2bfloat16(v.z), h3 = __float2bfloat16(v.w);
    __nv_bfloat16 l0 = __float2bfloat16(v.x - __bfloat162float(h0));
    __nv_bfloat16 l1 = __float2bfloat16(v.y - __bfloat162float(h1));
    __nv_bfloat16 l2 = __float2bfloat16(v.z - __bfloat162float(h2));
    __nv_bfloat16 l3 = __float2bfloat16(v.w - __bfloat162float(h3));
    uint2 ph, pl;
    ph.x = (unsigned)__bfloat16_as_ushort(h0) | ((unsigned)__bfloat16_as_ushort(h1) << 16);
    ph.y = (unsigned)__bfloat16_as_ushort(h2) | ((unsigned)__bfloat16_as_ushort(h3) << 16);
    pl.x = (unsigned)__bfloat16_as_ushort(l0) | ((unsigned)__bfloat16_as_ushort(l1) << 16);
    pl.y = (unsigned)__bfloat16_as_ushort(l2) | ((unsigned)__bfloat16_as_ushort(l3) << 16);
    *reinterpret_cast<uint2*>(g_Bhi + (size_t)r * KDIM + 4 * g) = ph;
    *reinterpret_cast<uint2*>(g_Blo + (size_t)r * KDIM + 4 * g) = pl;
}

// ---------------------------------------------------------------------------
// mma.sync GEMM: CTA 128x256, 8 warps (2M x 4N), warp tile 64x64.
// K-chunk 32 bf16 (64B/row), smem rows padded to 80B (conflict-free, 16B-aligned).
// ---------------------------------------------------------------------------
#define ROWB 80
#define OFF_AHI 0
#define OFF_ALO (BM * ROWB)                    // 10240
#define OFF_BHI (2 * BM * ROWB)                // 20480
#define OFF_BLO (2 * BM * ROWB + BN * ROWB)    // 40960
#define STAGE_BYTES (2 * (BM + BN) * ROWB)     // 61440
#define NSTAGE 3
#define SMEM_DYN (NSTAGE * STAGE_BYTES)        // 184320

__device__ __forceinline__ void load_chunk(unsigned stage, int m0, int n0, int k0, int tid) {
    #pragma unroll
    for (int j = 0; j < 2; j++) {              // A hi: 128 rows x 4 chunks
        int id = tid + (j << 8);
        int r = id >> 2, c = id & 3;
        cp16(stage + OFF_AHI + r * ROWB + c * 16,
             g_Ahi + ((size_t)(m0 + r) << 12) + k0 + (c << 3));
    }
    #pragma unroll
    for (int j = 0; j < 2; j++) {              // A lo
        int id = tid + (j << 8);
        int r = id >> 2, c = id & 3;
        cp16(stage + OFF_ALO + r * ROWB + c * 16,
             g_Alo + ((size_t)(m0 + r) << 12) + k0 + (c << 3));
    }
    #pragma unroll
    for (int j = 0; j < 4; j++) {              // B hi: 256 rows x 4 chunks
        int id = tid + (j << 8);
        int r = id >> 2, c = id & 3;
        cp16(stage + OFF_BHI + r * ROWB + c * 16,
             g_Bhi + ((size_t)(n0 + r) << 12) + k0 + (c << 3));
    }
    #pragma unroll
    for (int j = 0; j < 4; j++) {              // B lo
        int id = tid + (j << 8);
        int r = id >> 2, c = id & 3;
        cp16(stage + OFF_BLO + r * ROWB + c * 16,
             g_Blo + ((size_t)(n0 + r) << 12) + k0 + (c << 3));
    }
    CP_COMMIT();
}

__global__ __launch_bounds__(256, 1) void gemm_kernel(const int* __restrict__ indices,
                                                      float* __restrict__ out) {
    extern __shared__ char smem[];
    const unsigned sb = smem_u32(smem);
    const int tid = threadIdx.x, wid = tid >> 5, lane = tid & 31;
    const int wm = wid & 1, wn = wid >> 1;     // 2(M) x 4(N) warps
    const int sub = lane >> 3, lrow = lane & 7;

    const int tn = blockIdx.x & 15, tm = blockIdx.x >> 4;
    const int m0 = tm * BM, n0 = tn * BN;

    // per-thread ldmatrix base offsets (within a stage)
    // A frag (m16k16): sub0:(row,klo) sub1:(row+8,klo) sub2:(row,khi) sub3:(row+8,khi)
    const unsigned aoff = (unsigned)((wm * 64 + lrow + (sub & 1) * 8) * ROWB + (sub >> 1) * 16);
    // B frag pair (two n8k16): sub0:(row,klo) sub1:(row,khi) sub2:(row+8,klo) sub3:(row+8,khi)
    const unsigned boff = (unsigned)((wn * 64 + lrow + (sub >> 1) * 8) * ROWB + (sub & 1) * 16);

    float d[4][8][4];
    #pragma unroll
    for (int a = 0; a < 4; a++)
        #pragma unroll
        for (int b = 0; b < 8; b++)
            #pragma unroll
            for (int c = 0; c < 4; c++) d[a][b][c] = 0.f;

    load_chunk(sb,                   m0, n0, 0,       tid);
    load_chunk(sb + STAGE_BYTES,     m0, n0, BKE,     tid);

    int stage_idx = 0;
    for (int i = 0; i < NCHUNK; i++) {
        asm volatile("cp.async.wait_group 1;" ::: "memory");
        __syncthreads();
        const unsigned stg = sb + stage_idx * STAGE_BYTES;

        #pragma unroll
        for (int ks = 0; ks < 2; ks++) {
            unsigned ah[4][4], al[4][4], bh[4][4], bl[4][4];
            #pragma unroll
            for (int mt = 0; mt < 4; mt++) {
                ldsm4(ah[mt], stg + OFF_AHI + aoff + mt * (16 * ROWB) + ks * 32);
                ldsm4(al[mt], stg + OFF_ALO + aoff + mt * (16 * ROWB) + ks * 32);
            }
            #pragma unroll
            for (int p = 0; p < 4; p++) {
                ldsm4(bh[p], stg + OFF_BHI + boff + p * (16 * ROWB) + ks * 32);
                ldsm4(bl[p], stg + OFF_BLO + boff + p * (16 * ROWB) + ks * 32);
            }
            #pragma unroll
            for (int mt = 0; mt < 4; mt++)
                #pragma unroll
                for (int p = 0; p < 4; p++) {
                    mma16816(d[mt][2 * p],     ah[mt], &bh[p][0]);
                    mma16816(d[mt][2 * p + 1], ah[mt], &bh[p][2]);
                    mma16816(d[mt][2 * p],     ah[mt], &bl[p][0]);
                    mma16816(d[mt][2 * p + 1], ah[mt], &bl[p][2]);
                    mma16816(d[mt][2 * p],     al[mt], &bh[p][0]);
                    mma16816(d[mt][2 * p + 1], al[mt], &bh[p][2]);
                }
        }
        __syncthreads();
        if (i + 2 < NCHUNK)
            load_chunk(sb + ((stage_idx + 2) % NSTAGE) * STAGE_BYTES, m0, n0, (i + 2) * BKE, tid);
        else
            CP_COMMIT();
        stage_idx = (stage_idx + 1) % NSTAGE;
    }

    // Epilogue: scatter rows by indices, zero sibling rows.
    const int ncol = n0 + wn * 64 + 2 * (lane & 3);
    #pragma unroll
    for (int mt = 0; mt < 4; mt++) {
        #pragma unroll
        for (int h = 0; h < 2; h++) {
            const int r = m0 + wm * 64 + mt * 16 + h * 8 + (lane >> 2);
            const int idx = indices[r];
            float* orow = out + (size_t)idx * BATCH + ncol;
            float* zrow = out + (size_t)(idx ^ 1) * BATCH + ncol;
            #pragma unroll
            for (int j = 0; j < 8; j++) {
                float2 v = make_float2(d[mt][j][2 * h], d[mt][j][2 * h + 1]);
                *reinterpret_cast<float2*>(orow + 8 * j) = v;
                *reinterpret_cast<float2*>(zrow + 8 * j) = make_float2(0.f, 0.f);
            }
        }
    }
}

// ---------------------------------------------------------------------------
extern "C" void kernel_launch(void* const* d_in, const int* in_sizes, int n_in,
                              void* d_out, int out_size) {
    const float* weight   = (const float*)d_in[0];
    const int*   indices  = (const int*)  d_in[1];
    const int*   metadata = (const int*)  d_in[2];
    const float* input    = (const float*)d_in[3];
    float*       out      = (float*)d_out;

    cudaFuncSetAttribute(gemm_kernel, cudaFuncAttributeMaxDynamicSharedMemorySize, SMEM_DYN);

    convert_w<<<(OUT_F * (IN_F / 2)) / 256, 256>>>(weight, metadata);
    convert_in<<<(BATCH * (KDIM / 4)) / 256, 256>>>(input);
    gemm_kernel<<<(OUT_F / BM) * (BATCH / BN), 256, SMEM_DYN>>>(indices, out);
}

// round 15
// speedup vs baseline: 3.6989x; 1.5968x over previous
#include <cuda_runtime.h>
#include <cuda_fp16.h>

#define OUT_F 4096
#define IN_F  2048
#define KDIM  4096
#define BATCH 4096

#define BM 128
#define BN 256
#define BKE 64                    // K elems per chunk (4 x k16 mma steps)
#define NCHUNK (KDIM / BKE)       // 64

// ---- fp16 scratch: A split hi/lo (exact), B single fp16 (96 MB total) ----
__device__ __half g_Ah[(size_t)OUT_F * KDIM];
__device__ __half g_Al[(size_t)OUT_F * KDIM];
__device__ __half g_Bh[(size_t)BATCH * KDIM];

// ---------------------------------------------------------------------------
// helpers (arch-portable PTX only: sm_80-class, safe under compute_103)
// ---------------------------------------------------------------------------
__device__ __forceinline__ unsigned smem_u32(const void* p) {
    unsigned a;
    asm("{ .reg .u64 t; cvta.to.shared.u64 t, %1; cvt.u32.u64 %0, t; }" : "=r"(a) : "l"(p));
    return a;
}
__device__ __forceinline__ void cp16(unsigned dst, const void* src) {
    asm volatile("cp.async.cg.shared.global [%0], [%1], 16;" :: "r"(dst), "l"(src));
}
#define CP_COMMIT() asm volatile("cp.async.commit_group;" ::: "memory")

__device__ __forceinline__ void ldsm4(unsigned* r, unsigned addr) {
    asm volatile("ldmatrix.sync.aligned.m8n8.x4.shared.b16 {%0,%1,%2,%3}, [%4];"
                 : "=r"(r[0]), "=r"(r[1]), "=r"(r[2]), "=r"(r[3]) : "r"(addr));
}
__device__ __forceinline__ void mma16816(float* d, const unsigned* a, const unsigned* b) {
    asm volatile("mma.sync.aligned.m16n8k16.row.col.f32.f16.f16.f32 "
                 "{%0,%1,%2,%3}, {%4,%5,%6,%7}, {%8,%9}, {%0,%1,%2,%3};"
                 : "+f"(d[0]), "+f"(d[1]), "+f"(d[2]), "+f"(d[3])
                 : "r"(a[0]), "r"(a[1]), "r"(a[2]), "r"(a[3]), "r"(b[0]), "r"(b[1]));
}

__device__ __forceinline__ unsigned pack2(__half a, __half b) {
    return (unsigned)__half_as_ushort(a) | ((unsigned)__half_as_ushort(b) << 16);
}

// ---------------------------------------------------------------------------
// Convert: weight+meta -> dense fp16 hi/lo (A exact to ~2^-23)
// ---------------------------------------------------------------------------
__global__ void convert_w(const float* __restrict__ w, const int* __restrict__ meta) {
    int idx = blockIdx.x * 256 + threadIdx.x;   // r*1024 + g
    int r = idx >> 10, g = idx & 1023;
    const float2 wv = *reinterpret_cast<const float2*>(w    + (size_t)r * IN_F + 2 * g);
    const int2   mv = *reinterpret_cast<const int2*>  (meta + (size_t)r * IN_F + 2 * g);
    float v[4];
    v[0] = (mv.x == 0) ? wv.x : ((mv.y == 0) ? wv.y : 0.f);
    v[1] = (mv.x == 1) ? wv.x : ((mv.y == 1) ? wv.y : 0.f);
    v[2] = (mv.x == 2) ? wv.x : ((mv.y == 2) ? wv.y : 0.f);
    v[3] = (mv.x == 3) ? wv.x : ((mv.y == 3) ? wv.y : 0.f);
    __half h[4], l[4];
    #pragma unroll
    for (int i = 0; i < 4; i++) {
        h[i] = __float2half_rn(v[i]);
        l[i] = __float2half_rn(v[i] - __half2float(h[i]));
    }
    uint2 ph = make_uint2(pack2(h[0], h[1]), pack2(h[2], h[3]));
    uint2 pl = make_uint2(pack2(l[0], l[1]), pack2(l[2], l[3]));
    *reinterpret_cast<uint2*>(g_Ah + (size_t)r * KDIM + 4 * g) = ph;
    *reinterpret_cast<uint2*>(g_Al + (size_t)r * KDIM + 4 * g) = pl;
}

// Convert: input fp32 -> single fp16
__global__ void convert_in(const float* __restrict__ in) {
    int idx = blockIdx.x * 256 + threadIdx.x;   // row*1024 + g
    int r = idx >> 10, g = idx & 1023;
    const float4 v = *reinterpret_cast<const float4*>(in + (size_t)r * KDIM + 4 * g);
    uint2 p = make_uint2(pack2(__float2half_rn(v.x), __float2half_rn(v.y)),
                         pack2(__float2half_rn(v.z), __float2half_rn(v.w)));
    *reinterpret_cast<uint2*>(g_Bh + (size_t)r * KDIM + 4 * g) = p;
}

// ---------------------------------------------------------------------------
// mma.sync GEMM: CTA 128x256, 8 warps (2M x 4N), warp tile 64x64.
// K-chunk 64 fp16 (128B/row), rows padded to 144B (16B-aligned, conflict-free).
// D = Ah*Bh + Al*Bh  (2 MMAs per tile instead of 3)
// ---------------------------------------------------------------------------
#define ROWB 144
#define OFF_AH 0
#define OFF_AL (BM * ROWB)                     // 18432
#define OFF_BH (2 * BM * ROWB)                 // 36864
#define STAGE_BYTES ((2 * BM + BN) * ROWB)     // 73728
#define NSTAGE 3
#define SMEM_DYN (NSTAGE * STAGE_BYTES)        // 221184

__device__ __forceinline__ void load_chunk(unsigned stage, int m0, int n0, int k0, int tid) {
    #pragma unroll
    for (int j = 0; j < 4; j++) {              // A hi: 128 rows x 8 x 16B
        int id = tid + (j << 8);
        int r = id >> 3, c = id & 7;
        cp16(stage + OFF_AH + r * ROWB + c * 16,
             g_Ah + ((size_t)(m0 + r) << 12) + k0 + (c << 3));
    }
    #pragma unroll
    for (int j = 0; j < 4; j++) {              // A lo
        int id = tid + (j << 8);
        int r = id >> 3, c = id & 7;
        cp16(stage + OFF_AL + r * ROWB + c * 16,
             g_Al + ((size_t)(m0 + r) << 12) + k0 + (c << 3));
    }
    #pragma unroll
    for (int j = 0; j < 8; j++) {              // B hi: 256 rows x 8 x 16B
        int id = tid + (j << 8);
        int r = id >> 3, c = id & 7;
        cp16(stage + OFF_BH + r * ROWB + c * 16,
             g_Bh + ((size_t)(n0 + r) << 12) + k0 + (c << 3));
    }
    CP_COMMIT();
}

__global__ __launch_bounds__(256, 1) void gemm_kernel(const int* __restrict__ indices,
                                                      float* __restrict__ out) {
    extern __shared__ char smem[];
    const unsigned sb = smem_u32(smem);
    const int tid = threadIdx.x, wid = tid >> 5, lane = tid & 31;
    const int wm = wid & 1, wn = wid >> 1;     // 2(M) x 4(N) warps
    const int sub = lane >> 3, lrow = lane & 7;

    const int tn = blockIdx.x & 15, tm = blockIdx.x >> 4;
    const int m0 = tm * BM, n0 = tn * BN;

    // ldmatrix base offsets (within a stage, relative to ks*32 byte k-offset)
    const unsigned aoff = (unsigned)((wm * 64 + lrow + (sub & 1) * 8) * ROWB + (sub >> 1) * 16);
    const unsigned boff = (unsigned)((wn * 64 + lrow + (sub >> 1) * 8) * ROWB + (sub & 1) * 16);

    float d[4][8][4];
    #pragma unroll
    for (int a = 0; a < 4; a++)
        #pragma unroll
        for (int b = 0; b < 8; b++)
            #pragma unroll
            for (int c = 0; c < 4; c++) d[a][b][c] = 0.f;

    load_chunk(sb,               m0, n0, 0,   tid);
    load_chunk(sb + STAGE_BYTES, m0, n0, BKE, tid);

    int stage_idx = 0;
    for (int i = 0; i < NCHUNK; i++) {
        asm volatile("cp.async.wait_group 1;" ::: "memory");
        __syncthreads();
        const unsigned stg = sb + stage_idx * STAGE_BYTES;

        #pragma unroll
        for (int ks = 0; ks < 4; ks++) {       // 4 k16 steps per 64-elem chunk
            unsigned ah[4][4], al[4][4], bh[4][4];
            #pragma unroll
            for (int mt = 0; mt < 4; mt++) {
                ldsm4(ah[mt], stg + OFF_AH + aoff + mt * (16 * ROWB) + ks * 32);
                ldsm4(al[mt], stg + OFF_AL + aoff + mt * (16 * ROWB) + ks * 32);
            }
            #pragma unroll
            for (int p = 0; p < 4; p++)
                ldsm4(bh[p], stg + OFF_BH + boff + p * (16 * ROWB) + ks * 32);
            #pragma unroll
            for (int mt = 0; mt < 4; mt++)
                #pragma unroll
                for (int p = 0; p < 4; p++) {
                    mma16816(d[mt][2 * p],     ah[mt], &bh[p][0]);
                    mma16816(d[mt][2 * p + 1], ah[mt], &bh[p][2]);
                    mma16816(d[mt][2 * p],     al[mt], &bh[p][0]);
                    mma16816(d[mt][2 * p + 1], al[mt], &bh[p][2]);
                }
        }
        __syncthreads();
        if (i + 2 < NCHUNK)
            load_chunk(sb + ((stage_idx + 2) % NSTAGE) * STAGE_BYTES, m0, n0, (i + 2) * BKE, tid);
        else
            CP_COMMIT();   // keep wait_group counting consistent
        stage_idx = (stage_idx + 1) % NSTAGE;
    }

    // Epilogue: scatter rows by indices, zero sibling rows (full output covered).
    const int ncol = n0 + wn * 64 + 2 * (lane & 3);
    #pragma unroll
    for (int mt = 0; mt < 4; mt++) {
        #pragma unroll
        for (int h = 0; h < 2; h++) {
            const int r = m0 + wm * 64 + mt * 16 + h * 8 + (lane >> 2);
            const int idx = indices[r];
            float* orow = out + (size_t)idx * BATCH + ncol;
            float* zrow = out + (size_t)(idx ^ 1) * BATCH + ncol;
            #pragma unroll
            for (int j = 0; j < 8; j++) {
                *reinterpret_cast<float2*>(orow + 8 * j) =
                    make_float2(d[mt][j][2 * h], d[mt][j][2 * h + 1]);
                *reinterpret_cast<float2*>(zrow + 8 * j) = make_float2(0.f, 0.f);
            }
        }
    }
}

// ---------------------------------------------------------------------------
extern "C" void kernel_launch(void* const* d_in, const int* in_sizes, int n_in,
                              void* d_out, int out_size) {
    const float* weight   = (const float*)d_in[0];
    const int*   indices  = (const int*)  d_in[1];
    const int*   metadata = (const int*)  d_in[2];
    const float* input    = (const float*)d_in[3];
    float*       out      = (float*)d_out;

    cudaFuncSetAttribute(gemm_kernel, cudaFuncAttributeMaxDynamicSharedMemorySize, SMEM_DYN);

    convert_w<<<(OUT_F * (IN_F / 2)) / 256, 256>>>(weight, metadata);
    convert_in<<<(BATCH * (KDIM / 4)) / 256, 256>>>(input);
    gemm_kernel<<<(OUT_F / BM) * (BATCH / BN), 256, SMEM_DYN>>>(indices, out);
}

// round 16
// speedup vs baseline: 3.8246x; 1.0340x over previous
#include <cuda_runtime.h>
#include <cuda_fp16.h>

#define OUT_F 4096
#define IN_F  2048
#define KDIM  4096
#define BATCH 4096

#define BM 128
#define BN 256
#define BKE 64                    // K elems per chunk (4 x k16 mma steps)
#define NCHUNK (KDIM / BKE)       // 64
#define THREADS 512

// ---- fp16 scratch: A split hi/lo (exact), B single fp16 (96 MB total) ----
__device__ __half g_Ah[(size_t)OUT_F * KDIM];
__device__ __half g_Al[(size_t)OUT_F * KDIM];
__device__ __half g_Bh[(size_t)BATCH * KDIM];

// ---------------------------------------------------------------------------
// helpers (arch-portable PTX only: sm_80-class, safe under compute_103)
// ---------------------------------------------------------------------------
__device__ __forceinline__ unsigned smem_u32(const void* p) {
    unsigned a;
    asm("{ .reg .u64 t; cvta.to.shared.u64 t, %1; cvt.u32.u64 %0, t; }" : "=r"(a) : "l"(p));
    return a;
}
__device__ __forceinline__ void cp16(unsigned dst, const void* src) {
    asm volatile("cp.async.cg.shared.global [%0], [%1], 16;" :: "r"(dst), "l"(src));
}
#define CP_COMMIT() asm volatile("cp.async.commit_group;" ::: "memory")

__device__ __forceinline__ void ldsm4(unsigned* r, unsigned addr) {
    asm volatile("ldmatrix.sync.aligned.m8n8.x4.shared.b16 {%0,%1,%2,%3}, [%4];"
                 : "=r"(r[0]), "=r"(r[1]), "=r"(r[2]), "=r"(r[3]) : "r"(addr));
}
__device__ __forceinline__ void mma16816(float* d, const unsigned* a, const unsigned* b) {
    asm volatile("mma.sync.aligned.m16n8k16.row.col.f32.f16.f16.f32 "
                 "{%0,%1,%2,%3}, {%4,%5,%6,%7}, {%8,%9}, {%0,%1,%2,%3};"
                 : "+f"(d[0]), "+f"(d[1]), "+f"(d[2]), "+f"(d[3])
                 : "r"(a[0]), "r"(a[1]), "r"(a[2]), "r"(a[3]), "r"(b[0]), "r"(b[1]));
}

__device__ __forceinline__ unsigned pack2(__half a, __half b) {
    return (unsigned)__half_as_ushort(a) | ((unsigned)__half_as_ushort(b) << 16);
}

// ---------------------------------------------------------------------------
// Convert: weight+meta -> dense fp16 hi/lo (A exact to ~2^-23)
// ---------------------------------------------------------------------------
__global__ void convert_w(const float* __restrict__ w, const int* __restrict__ meta) {
    int idx = blockIdx.x * 256 + threadIdx.x;   // r*1024 + g
    int r = idx >> 10, g = idx & 1023;
    const float2 wv = *reinterpret_cast<const float2*>(w    + (size_t)r * IN_F + 2 * g);
    const int2   mv = *reinterpret_cast<const int2*>  (meta + (size_t)r * IN_F + 2 * g);
    float v[4];
    v[0] = (mv.x == 0) ? wv.x : ((mv.y == 0) ? wv.y : 0.f);
    v[1] = (mv.x == 1) ? wv.x : ((mv.y == 1) ? wv.y : 0.f);
    v[2] = (mv.x == 2) ? wv.x : ((mv.y == 2) ? wv.y : 0.f);
    v[3] = (mv.x == 3) ? wv.x : ((mv.y == 3) ? wv.y : 0.f);
    __half h[4], l[4];
    #pragma unroll
    for (int i = 0; i < 4; i++) {
        h[i] = __float2half_rn(v[i]);
        l[i] = __float2half_rn(v[i] - __half2float(h[i]));
    }
    uint2 ph = make_uint2(pack2(h[0], h[1]), pack2(h[2], h[3]));
    uint2 pl = make_uint2(pack2(l[0], l[1]), pack2(l[2], l[3]));
    *reinterpret_cast<uint2*>(g_Ah + (size_t)r * KDIM + 4 * g) = ph;
    *reinterpret_cast<uint2*>(g_Al + (size_t)r * KDIM + 4 * g) = pl;
}

// Convert: input fp32 -> single fp16
__global__ void convert_in(const float* __restrict__ in) {
    int idx = blockIdx.x * 256 + threadIdx.x;   // row*1024 + g
    int r = idx >> 10, g = idx & 1023;
    const float4 v = *reinterpret_cast<const float4*>(in + (size_t)r * KDIM + 4 * g);
    uint2 p = make_uint2(pack2(__float2half_rn(v.x), __float2half_rn(v.y)),
                         pack2(__float2half_rn(v.z), __float2half_rn(v.w)));
    *reinterpret_cast<uint2*>(g_Bh + (size_t)r * KDIM + 4 * g) = p;
}

// ---------------------------------------------------------------------------
// mma.sync GEMM: CTA 128x256, 16 warps (4M x 4N), warp tile 32x64.
// K-chunk 64 fp16 (128B/row), rows padded to 144B (16B-aligned, conflict-free).
// D = Ah*Bh + Al*Bh; register-fragment double buffering across k16 steps.
// ---------------------------------------------------------------------------
#define ROWB 144
#define OFF_AH 0
#define OFF_AL (BM * ROWB)                     // 18432
#define OFF_BH (2 * BM * ROWB)                 // 36864
#define STAGE_BYTES ((2 * BM + BN) * ROWB)     // 73728
#define NSTAGE 3
#define SMEM_DYN (NSTAGE * STAGE_BYTES)        // 221184

__device__ __forceinline__ void load_chunk(unsigned stage, int m0, int n0, int k0, int tid) {
    #pragma unroll
    for (int j = 0; j < 2; j++) {              // A hi: 128 rows x 8 x 16B = 1024
        int id = tid + (j << 9);
        int r = id >> 3, c = id & 7;
        cp16(stage + OFF_AH + r * ROWB + c * 16,
             g_Ah + ((size_t)(m0 + r) << 12) + k0 + (c << 3));
    }
    #pragma unroll
    for (int j = 0; j < 2; j++) {              // A lo
        int id = tid + (j << 9);
        int r = id >> 3, c = id & 7;
        cp16(stage + OFF_AL + r * ROWB + c * 16,
             g_Al + ((size_t)(m0 + r) << 12) + k0 + (c << 3));
    }
    #pragma unroll
    for (int j = 0; j < 4; j++) {              // B hi: 256 rows x 8 x 16B = 2048
        int id = tid + (j << 9);
        int r = id >> 3, c = id & 7;
        cp16(stage + OFF_BH + r * ROWB + c * 16,
             g_Bh + ((size_t)(n0 + r) << 12) + k0 + (c << 3));
    }
    CP_COMMIT();
}

__device__ __forceinline__ void load_frags(unsigned stg, unsigned aoff, unsigned boff, int ks,
                                           unsigned ah[2][4], unsigned al[2][4],
                                           unsigned bh[4][4]) {
    #pragma unroll
    for (int mt = 0; mt < 2; mt++) {
        ldsm4(ah[mt], stg + OFF_AH + aoff + mt * (16 * ROWB) + ks * 32);
        ldsm4(al[mt], stg + OFF_AL + aoff + mt * (16 * ROWB) + ks * 32);
    }
    #pragma unroll
    for (int p = 0; p < 4; p++)
        ldsm4(bh[p], stg + OFF_BH + boff + p * (16 * ROWB) + ks * 32);
}

__global__ __launch_bounds__(THREADS, 1) void gemm_kernel(const int* __restrict__ indices,
                                                          float* __restrict__ out) {
    extern __shared__ char smem[];
    const unsigned sb = smem_u32(smem);
    const int tid = threadIdx.x, wid = tid >> 5, lane = tid & 31;
    const int wm = wid & 3, wn = wid >> 2;     // 4(M) x 4(N) warps
    const int sub = lane >> 3, lrow = lane & 7;

    const int tn = blockIdx.x & 15, tm = blockIdx.x >> 4;
    const int m0 = tm * BM, n0 = tn * BN;

    // ldmatrix base offsets (within a stage, k-offset added per ks)
    const unsigned aoff = (unsigned)((wm * 32 + lrow + (sub & 1) * 8) * ROWB + (sub >> 1) * 16);
    const unsigned boff = (unsigned)((wn * 64 + lrow + (sub >> 1) * 8) * ROWB + (sub & 1) * 16);

    float d[2][8][4];
    #pragma unroll
    for (int a = 0; a < 2; a++)
        #pragma unroll
        for (int b = 0; b < 8; b++)
            #pragma unroll
            for (int c = 0; c < 4; c++) d[a][b][c] = 0.f;

    load_chunk(sb,               m0, n0, 0,   tid);
    load_chunk(sb + STAGE_BYTES, m0, n0, BKE, tid);

    int stage_idx = 0;
    for (int i = 0; i < NCHUNK; i++) {
        asm volatile("cp.async.wait_group 1;" ::: "memory");
        __syncthreads();
        const unsigned stg = sb + stage_idx * STAGE_BYTES;

        // issue next-next chunk loads early; target stage's reads finished
        // before this iteration's barrier (3-stage ring), so no extra sync.
        if (i + 2 < NCHUNK)
            load_chunk(sb + ((stage_idx + 2) % NSTAGE) * STAGE_BYTES, m0, n0, (i + 2) * BKE, tid);
        else
            CP_COMMIT();   // keep wait_group counting consistent

        unsigned ah[2][2][4], al[2][2][4], bh[2][4][4];
        load_frags(stg, aoff, boff, 0, ah[0], al[0], bh[0]);

        #pragma unroll
        for (int ks = 0; ks < 4; ks++) {
            const int cur = ks & 1;
            if (ks < 3)
                load_frags(stg, aoff, boff, ks + 1, ah[cur ^ 1], al[cur ^ 1], bh[cur ^ 1]);
            // 16 ah-products, then 16 al-products: accumulator reuse distance 16
            #pragma unroll
            for (int mt = 0; mt < 2; mt++)
                #pragma unroll
                for (int p = 0; p < 4; p++) {
                    mma16816(d[mt][2 * p],     ah[cur][mt], &bh[cur][p][0]);
                    mma16816(d[mt][2 * p + 1], ah[cur][mt], &bh[cur][p][2]);
                }
            #pragma unroll
            for (int mt = 0; mt < 2; mt++)
                #pragma unroll
                for (int p = 0; p < 4; p++) {
                    mma16816(d[mt][2 * p],     al[cur][mt], &bh[cur][p][0]);
                    mma16816(d[mt][2 * p + 1], al[cur][mt], &bh[cur][p][2]);
                }
        }
        stage_idx = (stage_idx + 1) % NSTAGE;
    }

    // Epilogue: scatter rows by indices, zero sibling rows (full output covered).
    const int ncol = n0 + wn * 64 + 2 * (lane & 3);
    #pragma unroll
    for (int mt = 0; mt < 2; mt++) {
        #pragma unroll
        for (int h = 0; h < 2; h++) {
            const int r = m0 + wm * 32 + mt * 16 + h * 8 + (lane >> 2);
            const int idx = indices[r];
            float* orow = out + (size_t)idx * BATCH + ncol;
            float* zrow = out + (size_t)(idx ^ 1) * BATCH + ncol;
            #pragma unroll
            for (int j = 0; j < 8; j++) {
                *reinterpret_cast<float2*>(orow + 8 * j) =
                    make_float2(d[mt][j][2 * h], d[mt][j][2 * h + 1]);
                *reinterpret_cast<float2*>(zrow + 8 * j) = make_float2(0.f, 0.f);
            }
        }
    }
}

// ---------------------------------------------------------------------------
extern "C" void kernel_launch(void* const* d_in, const int* in_sizes, int n_in,
                              void* d_out, int out_size) {
    const float* weight   = (const float*)d_in[0];
    const int*   indices  = (const int*)  d_in[1];
    const int*   metadata = (const int*)  d_in[2];
    const float* input    = (const float*)d_in[3];
    float*       out      = (float*)d_out;

    cudaFuncSetAttribute(gemm_kernel, cudaFuncAttributeMaxDynamicSharedMemorySize, SMEM_DYN);

    convert_w<<<(OUT_F * (IN_F / 2)) / 256, 256>>>(weight, metadata);
    convert_in<<<(BATCH * (KDIM / 4)) / 256, 256>>>(input);
    gemm_kernel<<<(OUT_F / BM) * (BATCH / BN), THREADS, SMEM_DYN>>>(indices, out);
}

// round 17
// speedup vs baseline: 5.9640x; 1.5594x over previous
#include <cuda_runtime.h>
#include <cuda_fp16.h>

#define OUT_F 4096
#define IN_F  2048
#define KDIM  4096
#define BATCH 4096

#define BM 128
#define BN 256
#define BKE 64                    // K elems per chunk (4 x k16 mma steps)
#define NCHUNK (KDIM / BKE)       // 64
#define THREADS 512

// ---- fp16 scratch: A single fp16, B single fp16 (64 MB total) ----
__device__ __half g_A[(size_t)OUT_F * KDIM];
__device__ __half g_B[(size_t)BATCH * KDIM];

// ---------------------------------------------------------------------------
// helpers (arch-portable PTX only: sm_80-class, safe under compute_103)
// ---------------------------------------------------------------------------
__device__ __forceinline__ unsigned smem_u32(const void* p) {
    unsigned a;
    asm("{ .reg .u64 t; cvta.to.shared.u64 t, %1; cvt.u32.u64 %0, t; }" : "=r"(a) : "l"(p));
    return a;
}
__device__ __forceinline__ void cp16(unsigned dst, const void* src) {
    asm volatile("cp.async.cg.shared.global [%0], [%1], 16;" :: "r"(dst), "l"(src));
}
#define CP_COMMIT() asm volatile("cp.async.commit_group;" ::: "memory")

__device__ __forceinline__ void ldsm4(unsigned* r, unsigned addr) {
    asm volatile("ldmatrix.sync.aligned.m8n8.x4.shared.b16 {%0,%1,%2,%3}, [%4];"
                 : "=r"(r[0]), "=r"(r[1]), "=r"(r[2]), "=r"(r[3]) : "r"(addr));
}
__device__ __forceinline__ void mma16816(float* d, const unsigned* a, const unsigned* b) {
    asm volatile("mma.sync.aligned.m16n8k16.row.col.f32.f16.f16.f32 "
                 "{%0,%1,%2,%3}, {%4,%5,%6,%7}, {%8,%9}, {%0,%1,%2,%3};"
                 : "+f"(d[0]), "+f"(d[1]), "+f"(d[2]), "+f"(d[3])
                 : "r"(a[0]), "r"(a[1]), "r"(a[2]), "r"(a[3]), "r"(b[0]), "r"(b[1]));
}

__device__ __forceinline__ unsigned pack2(__half a, __half b) {
    return (unsigned)__half_as_ushort(a) | ((unsigned)__half_as_ushort(b) << 16);
}

// ---------------------------------------------------------------------------
// Convert: weight+meta -> dense fp16
// ---------------------------------------------------------------------------
__global__ void convert_w(const float* __restrict__ w, const int* __restrict__ meta) {
    int idx = blockIdx.x * 256 + threadIdx.x;   // r*1024 + g
    int r = idx >> 10, g = idx & 1023;
    const float2 wv = *reinterpret_cast<const float2*>(w    + (size_t)r * IN_F + 2 * g);
    const int2   mv = *reinterpret_cast<const int2*>  (meta + (size_t)r * IN_F + 2 * g);
    float v[4];
    v[0] = (mv.x == 0) ? wv.x : ((mv.y == 0) ? wv.y : 0.f);
    v[1] = (mv.x == 1) ? wv.x : ((mv.y == 1) ? wv.y : 0.f);
    v[2] = (mv.x == 2) ? wv.x : ((mv.y == 2) ? wv.y : 0.f);
    v[3] = (mv.x == 3) ? wv.x : ((mv.y == 3) ? wv.y : 0.f);
    uint2 p = make_uint2(pack2(__float2half_rn(v[0]), __float2half_rn(v[1])),
                         pack2(__float2half_rn(v[2]), __float2half_rn(v[3])));
    *reinterpret_cast<uint2*>(g_A + (size_t)r * KDIM + 4 * g) = p;
}

// Convert: input fp32 -> fp16
__global__ void convert_in(const float* __restrict__ in) {
    int idx = blockIdx.x * 256 + threadIdx.x;   // row*1024 + g
    int r = idx >> 10, g = idx & 1023;
    const float4 v = *reinterpret_cast<const float4*>(in + (size_t)r * KDIM + 4 * g);
    uint2 p = make_uint2(pack2(__float2half_rn(v.x), __float2half_rn(v.y)),
                         pack2(__float2half_rn(v.z), __float2half_rn(v.w)));
    *reinterpret_cast<uint2*>(g_B + (size_t)r * KDIM + 4 * g) = p;
}

// ---------------------------------------------------------------------------
// mma.sync GEMM: CTA 128x256, 16 warps (4M x 4N), warp tile 32x64.
// Single fp16 product (input-rounding error only, ~2.9e-4 rel).
// K-chunk 64 fp16 (128B/row), rows padded to 144B; 4-stage cp.async pipeline.
// ---------------------------------------------------------------------------
#define ROWB 144
#define OFF_A 0
#define OFF_B (BM * ROWB)                      // 18432
#define STAGE_BYTES ((BM + BN) * ROWB)         // 55296
#define NSTAGE 4
#define SMEM_DYN (NSTAGE * STAGE_BYTES)        // 221184

__device__ __forceinline__ void load_chunk(unsigned stage, int m0, int n0, int k0, int tid) {
    #pragma unroll
    for (int j = 0; j < 2; j++) {              // A: 128 rows x 8 x 16B = 1024
        int id = tid + (j << 9);
        int r = id >> 3, c = id & 7;
        cp16(stage + OFF_A + r * ROWB + c * 16,
             g_A + ((size_t)(m0 + r) << 12) + k0 + (c << 3));
    }
    #pragma unroll
    for (int j = 0; j < 4; j++) {              // B: 256 rows x 8 x 16B = 2048
        int id = tid + (j << 9);
        int r = id >> 3, c = id & 7;
        cp16(stage + OFF_B + r * ROWB + c * 16,
             g_B + ((size_t)(n0 + r) << 12) + k0 + (c << 3));
    }
    CP_COMMIT();
}

__device__ __forceinline__ void load_frags(unsigned stg, unsigned aoff, unsigned boff, int ks,
                                           unsigned ah[2][4], unsigned bh[4][4]) {
    #pragma unroll
    for (int mt = 0; mt < 2; mt++)
        ldsm4(ah[mt], stg + OFF_A + aoff + mt * (16 * ROWB) + ks * 32);
    #pragma unroll
    for (int p = 0; p < 4; p++)
        ldsm4(bh[p], stg + OFF_B + boff + p * (16 * ROWB) + ks * 32);
}

__global__ __launch_bounds__(THREADS, 1) void gemm_kernel(const int* __restrict__ indices,
                                                          float* __restrict__ out) {
    extern __shared__ char smem[];
    const unsigned sb = smem_u32(smem);
    const int tid = threadIdx.x, wid = tid >> 5, lane = tid & 31;
    const int wm = wid & 3, wn = wid >> 2;     // 4(M) x 4(N) warps
    const int sub = lane >> 3, lrow = lane & 7;

    const int tn = blockIdx.x & 15, tm = blockIdx.x >> 4;
    const int m0 = tm * BM, n0 = tn * BN;

    // ldmatrix base offsets (within a stage, k-offset added per ks)
    const unsigned aoff = (unsigned)((wm * 32 + lrow + (sub & 1) * 8) * ROWB + (sub >> 1) * 16);
    const unsigned boff = (unsigned)((wn * 64 + lrow + (sub >> 1) * 8) * ROWB + (sub & 1) * 16);

    float d[2][8][4];
    #pragma unroll
    for (int a = 0; a < 2; a++)
        #pragma unroll
        for (int b = 0; b < 8; b++)
            #pragma unroll
            for (int c = 0; c < 4; c++) d[a][b][c] = 0.f;

    load_chunk(sb,                   m0, n0, 0,       tid);
    load_chunk(sb + STAGE_BYTES,     m0, n0, BKE,     tid);
    load_chunk(sb + 2 * STAGE_BYTES, m0, n0, 2 * BKE, tid);

    int stage_idx = 0;
    for (int i = 0; i < NCHUNK; i++) {
        asm volatile("cp.async.wait_group 2;" ::: "memory");
        __syncthreads();
        const unsigned stg = sb + stage_idx * STAGE_BYTES;

        // issue chunk i+3 into stage (i+3)%4: its last reads finished before
        // the barrier at iteration i-1 < i, so no extra sync needed.
        if (i + 3 < NCHUNK)
            load_chunk(sb + ((stage_idx + 3) & 3) * STAGE_BYTES, m0, n0, (i + 3) * BKE, tid);
        else
            CP_COMMIT();   // keep wait_group counting consistent

        unsigned ah[2][2][4], bh[2][4][4];
        load_frags(stg, aoff, boff, 0, ah[0], bh[0]);

        #pragma unroll
        for (int ks = 0; ks < 4; ks++) {
            const int cur = ks & 1;
            if (ks < 3)
                load_frags(stg, aoff, boff, ks + 1, ah[cur ^ 1], bh[cur ^ 1]);
            #pragma unroll
            for (int mt = 0; mt < 2; mt++)
                #pragma unroll
                for (int p = 0; p < 4; p++) {
                    mma16816(d[mt][2 * p],     ah[cur][mt], &bh[cur][p][0]);
                    mma16816(d[mt][2 * p + 1], ah[cur][mt], &bh[cur][p][2]);
                }
        }
        stage_idx = (stage_idx + 1) & 3;
    }

    // Epilogue: scatter rows by indices, zero sibling rows (full output covered).
    const int ncol = n0 + wn * 64 + 2 * (lane & 3);
    #pragma unroll
    for (int mt = 0; mt < 2; mt++) {
        #pragma unroll
        for (int h = 0; h < 2; h++) {
            const int r = m0 + wm * 32 + mt * 16 + h * 8 + (lane >> 2);
            const int idx = indices[r];
            float* orow = out + (size_t)idx * BATCH + ncol;
            float* zrow = out + (size_t)(idx ^ 1) * BATCH + ncol;
            #pragma unroll
            for (int j = 0; j < 8; j++) {
                *reinterpret_cast<float2*>(orow + 8 * j) =
                    make_float2(d[mt][j][2 * h], d[mt][j][2 * h + 1]);
                *reinterpret_cast<float2*>(zrow + 8 * j) = make_float2(0.f, 0.f);
            }
        }
    }
}

// ---------------------------------------------------------------------------
extern "C" void kernel_launch(void* const* d_in, const int* in_sizes, int n_in,
                              void* d_out, int out_size) {
    const float* weight   = (const float*)d_in[0];
    const int*   indices  = (const int*)  d_in[1];
    const int*   metadata = (const int*)  d_in[2];
    const float* input    = (const float*)d_in[3];
    float*       out      = (float*)d_out;

    cudaFuncSetAttribute(gemm_kernel, cudaFuncAttributeMaxDynamicSharedMemorySize, SMEM_DYN);

    convert_w<<<(OUT_F * (IN_F / 2)) / 256, 256>>>(weight, metadata);
    convert_in<<<(BATCH * (KDIM / 4)) / 256, 256>>>(input);
    gemm_kernel<<<(OUT_F / BM) * (BATCH / BN), THREADS, SMEM_DYN>>>(indices, out);
}